// round 14
// baseline (speedup 1.0000x reference)
#include <cuda_runtime.h>
#include <cuda_fp16.h>
#include <math.h>
#include <stdint.h>

#define BATCH 4
#define SEQ   1024
#define DIM   1024
#define NH    16
#define HS    64
#define NL    4
#define FFD   4096
#define VOCAB 32000
#define ROWS  (BATCH * SEQ)
#define NSLAB (VOCAB / 256)            // 125 (LM CTA tile is 256 wide)

// ---------------------------------------------------------------------------
// Scratch
// ---------------------------------------------------------------------------
__device__ float  g_x   [(size_t)ROWS * DIM];        // residual (fp32)
__device__ __half g_hh  [(size_t)ROWS * DIM];        // LN output (fp16)
__device__ __half g_qkvh[(size_t)ROWS * 3 * DIM];    // q|k|v per row (fp16)
__device__ __half g_oh  [(size_t)ROWS * DIM];        // attn output (fp16)
__device__ __half g_ffh [(size_t)ROWS * FFD];        // MLP hidden (fp16)
__device__ __half g_wth [(size_t)VOCAB * DIM];       // transposed weights (fp16)
__device__ float2 g_part[(size_t)ROWS * NSLAB];      // per-slab (max, sumexp)
__device__ float  g_zt  [ROWS];                      // target logits
__device__ float  g_rl  [ROWS];

// ---------------------------------------------------------------------------
// Helpers
// ---------------------------------------------------------------------------
__device__ __forceinline__ uint32_t s2u(const void* p) {
    uint32_t a;
    asm("{ .reg .u64 t; cvta.to.shared.u64 t, %1; cvt.u32.u64 %0, t; }" : "=r"(a) : "l"(p));
    return a;
}
__device__ __forceinline__ void cpa16(uint32_t dst, const void* src) {
    asm volatile("cp.async.cg.shared.global [%0], [%1], 16;" :: "r"(dst), "l"(src));
}
__device__ __forceinline__ void hmma(float* c, uint32_t a0, uint32_t a1, uint32_t a2,
                                     uint32_t a3, uint32_t b0, uint32_t b1) {
    asm volatile(
        "mma.sync.aligned.m16n8k16.row.col.f32.f16.f16.f32 "
        "{%0,%1,%2,%3}, {%4,%5,%6,%7}, {%8,%9}, {%0,%1,%2,%3};"
        : "+f"(c[0]), "+f"(c[1]), "+f"(c[2]), "+f"(c[3])
        : "r"(a0), "r"(a1), "r"(a2), "r"(a3), "r"(b0), "r"(b1));
}
__device__ __forceinline__ void ldsm4(uint32_t* d, uint32_t addr) {
    asm volatile("ldmatrix.sync.aligned.m8n8.x4.shared.b16 {%0,%1,%2,%3}, [%4];"
                 : "=r"(d[0]), "=r"(d[1]), "=r"(d[2]), "=r"(d[3]) : "r"(addr));
}
__device__ __forceinline__ void ldsm4t(uint32_t* d, uint32_t addr) {
    asm volatile("ldmatrix.sync.aligned.m8n8.x4.trans.shared.b16 {%0,%1,%2,%3}, [%4];"
                 : "=r"(d[0]), "=r"(d[1]), "=r"(d[2]), "=r"(d[3]) : "r"(addr));
}
// e^x for x <= 0, FFMA/ALU-pipe polynomial (relieves MUFU)
__device__ __forceinline__ float exp_poly(float x) {
    float z = x * 1.4426950408889634f;
    float t = z + 12582912.0f;
    float n = t - 12582912.0f;
    float f = z - n;
    float p = 1.3333558e-3f;
    p = fmaf(p, f, 9.6181291e-3f);
    p = fmaf(p, f, 5.5504109e-2f);
    p = fmaf(p, f, 2.4022651e-1f);
    p = fmaf(p, f, 6.9314718e-1f);
    p = fmaf(p, f, 1.0f);
    float sc = __int_as_float((((int)n) + 127) << 23);
    return (x < -80.f) ? 0.f : p * sc;
}

// ---------------------------------------------------------------------------
// Embedding
// ---------------------------------------------------------------------------
__global__ void embed_kernel(const int* __restrict__ idx,
                             const float* __restrict__ tok,
                             const float* __restrict__ pos,
                             float* __restrict__ x)
{
    int row = blockIdx.x;
    int t   = row & (SEQ - 1);
    int tk  = idx[row];
    const float* te = tok + (size_t)tk * DIM;
    const float* pe = pos + (size_t)t * DIM;
    float* xr = x + (size_t)row * DIM;
    for (int i = threadIdx.x; i < DIM; i += blockDim.x)
        xr[i] = te[i] + pe[i];
}

// ---------------------------------------------------------------------------
// LayerNorm -> fp16, warp-per-row (8 rows per 256-thread CTA)
// ---------------------------------------------------------------------------
__global__ __launch_bounds__(256)
void ln_kernel(const float* __restrict__ x,
               const float* __restrict__ g,
               const float* __restrict__ b,
               __half* __restrict__ y)
{
    int w = threadIdx.x >> 5, l = threadIdx.x & 31;
    int row = blockIdx.x * 8 + w;
    const float4* xr = (const float4*)(x + (size_t)row * DIM);
    float4 v[8];
    float s = 0.f, ss = 0.f;
#pragma unroll
    for (int j = 0; j < 8; j++) {
        v[j] = xr[l + 32 * j];
        s  += v[j].x + v[j].y + v[j].z + v[j].w;
        ss += v[j].x * v[j].x + v[j].y * v[j].y + v[j].z * v[j].z + v[j].w * v[j].w;
    }
#pragma unroll
    for (int st = 16; st > 0; st >>= 1) {
        s  += __shfl_xor_sync(0xFFFFFFFF, s, st);
        ss += __shfl_xor_sync(0xFFFFFFFF, ss, st);
    }
    float mean = s * (1.0f / DIM);
    float var  = fmaxf(ss * (1.0f / DIM) - mean * mean, 0.f);
    float rstd = rsqrtf(var + 1e-5f);
    const float4* g4 = (const float4*)g;
    const float4* b4 = (const float4*)b;
    __half2* yr = (__half2*)(y + (size_t)row * DIM);
#pragma unroll
    for (int j = 0; j < 8; j++) {
        int i4 = l + 32 * j;
        float4 gg = g4[i4], bb = b4[i4];
        float o0 = (v[j].x - mean) * rstd * gg.x + bb.x;
        float o1 = (v[j].y - mean) * rstd * gg.y + bb.y;
        float o2 = (v[j].z - mean) * rstd * gg.z + bb.z;
        float o3 = (v[j].w - mean) * rstd * gg.w + bb.w;
        yr[i4 * 2]     = __halves2half2(__float2half(o0), __float2half(o1));
        yr[i4 * 2 + 1] = __halves2half2(__float2half(o2), __float2half(o3));
    }
}

// ---------------------------------------------------------------------------
// Pack Wq|Wk|Wv -> [3*DIM][DIM] K-major fp16, coalesced via smem tile.
// ---------------------------------------------------------------------------
__global__ void pack_qkv_t(const float* __restrict__ Wq,
                           const float* __restrict__ Wk,
                           const float* __restrict__ Wv,
                           __half* __restrict__ out, int l)
{
    __shared__ float t[32][33];
    int z = blockIdx.z;                    // which*16 + h
    int which = z >> 4, h = z & 15;
    int s0 = blockIdx.x * 32, d0 = blockIdx.y * 32;
    int x = threadIdx.x, y = threadIdx.y;
    const float* W = (which == 0) ? Wq : (which == 1) ? Wk : Wv;
    const float* base = W + ((size_t)l * NH + h) * DIM * HS;     // [DIM][HS]
#pragma unroll
    for (int j = 0; j < 4; j++)
        t[y + 8 * j][x] = base[(size_t)(d0 + y + 8 * j) * HS + s0 + x];
    __syncthreads();
    __half* o = out + (size_t)(which * 1024 + h * 64) * DIM;
#pragma unroll
    for (int j = 0; j < 4; j++)
        o[(size_t)(s0 + y + 8 * j) * DIM + d0 + x] = __float2half(t[x][y + 8 * j]);
}

// ---------------------------------------------------------------------------
// Transpose [R][C] fp32 -> [C][R] fp16
// ---------------------------------------------------------------------------
__global__ void transpose_k(const float* __restrict__ in, __half* __restrict__ out,
                            int R, int C)
{
    __shared__ float t[32][33];
    int c0 = blockIdx.x * 32, r0 = blockIdx.y * 32;
    int x = threadIdx.x, y = threadIdx.y;
#pragma unroll
    for (int j = 0; j < 4; j++)
        t[y + 8 * j][x] = in[(size_t)(r0 + y + 8 * j) * C + c0 + x];
    __syncthreads();
#pragma unroll
    for (int j = 0; j < 4; j++)
        out[(size_t)(c0 + y + 8 * j) * R + r0 + x] = __float2half(t[x][y + 8 * j]);
}

// ---------------------------------------------------------------------------
// fp16 HMMA GEMM: BK=64, XOR-swizzled smem, ldmatrix, 3-stage pipeline.
// (R11-proven mainloop)
// ---------------------------------------------------------------------------
#define BK 64
#define TILEB (128 * BK * 2)           // 16384 B per operand tile
#define GEMM_SMEM (6 * TILEB)          // 3 stages x (A,B) = 96 KB

#define GEMM_PRE()                                                            \
    extern __shared__ __half smh[];                                           \
    uint32_t sA = s2u(smh);                                                   \
    uint32_t sB = sA + 3 * TILEB;                                             \
    const int tid = threadIdx.x;                                              \
    const int bn = blockIdx.x * 128;                                          \
    const int bm = blockIdx.y * 128;                                          \
    const int wid = tid >> 5, l = tid & 31;                                   \
    const int wm = (wid & 1) * 64;                                            \
    const int wn = (wid >> 1) * 32;                                           \
    const int nt = K / BK;                                                    \
    const int c2 = (l & 3) * 2;                                               \
    const int lq = l >> 2;                                                    \
    const int ldr = tid >> 3;              /* 0..31 */                        \
    const int ldc8 = tid & 7;              /* chunk col */                    \
    const __half* Ag = A  + (size_t)(bm + ldr) * K + ldc8 * 8;                \
    const __half* Bg = Bt + (size_t)(bn + ldr) * K + ldc8 * 8;                \
    const uint32_t sAo = sA + (ldr * BK + ((ldc8 ^ (ldr & 7)) * 8)) * 2;      \
    const uint32_t sBo = sB + (ldr * BK + ((ldc8 ^ (ldr & 7)) * 8)) * 2;      \
    float acc[4][4][4];                                                       \
    _Pragma("unroll")                                                         \
    for (int i = 0; i < 4; i++)                                               \
        _Pragma("unroll")                                                     \
        for (int j = 0; j < 4; j++)                                           \
            _Pragma("unroll")                                                 \
            for (int c = 0; c < 4; c++) acc[i][j][c] = 0.f;                   \
    const int a_row  = l & 15;                                                \
    const int a_kch  = l >> 4;                                                \
    const int b_nrow = (l & 7) + ((l >> 4) << 3);                             \
    const int b_kch  = (l >> 3) & 1;

#define LOAD_TILE(T)                                                          \
    {                                                                         \
        int buf_ = (T) % 3;                                                   \
        int ko_ = (T) * BK;                                                   \
        _Pragma("unroll")                                                     \
        for (int p = 0; p < 4; p++) {                                         \
            cpa16(sAo + buf_ * TILEB + p * 32 * BK * 2,                       \
                  Ag + (size_t)(p * 32) * K + ko_);                           \
            cpa16(sBo + buf_ * TILEB + p * 32 * BK * 2,                       \
                  Bg + (size_t)(p * 32) * K + ko_);                           \
        }                                                                     \
        asm volatile("cp.async.commit_group;" ::: "memory");                  \
    }

#define GEMM_MAINLOOP()                                                       \
    LOAD_TILE(0);                                                             \
    if (nt > 1) LOAD_TILE(1);                                                 \
    for (int t = 0; t < nt; t++) {                                            \
        if (t + 1 < nt) { asm volatile("cp.async.wait_group 1;" ::: "memory"); } \
        else            { asm volatile("cp.async.wait_group 0;" ::: "memory"); } \
        __syncthreads();                                                      \
        if (t + 2 < nt) LOAD_TILE(t + 2);                                     \
        uint32_t Ab = sA + (t % 3) * TILEB;                                   \
        uint32_t Bb = sB + (t % 3) * TILEB;                                   \
        _Pragma("unroll")                                                     \
        for (int kk = 0; kk < 4; kk++) {                                      \
            uint32_t a[4][4], bfr[2][4];                                      \
            _Pragma("unroll")                                                 \
            for (int im = 0; im < 4; im++) {                                  \
                int row_ = wm + im * 16 + a_row;                              \
                int ch_ = (kk * 2 + a_kch) ^ (row_ & 7);                      \
                ldsm4(a[im], Ab + (row_ * BK + ch_ * 8) * 2);                 \
            }                                                                 \
            _Pragma("unroll")                                                 \
            for (int g = 0; g < 2; g++) {                                     \
                int row_ = wn + g * 16 + b_nrow;                              \
                int ch_ = (kk * 2 + b_kch) ^ (row_ & 7);                      \
                ldsm4(bfr[g], Bb + (row_ * BK + ch_ * 8) * 2);                \
            }                                                                 \
            _Pragma("unroll")                                                 \
            for (int im = 0; im < 4; im++)                                    \
                _Pragma("unroll")                                             \
                for (int in = 0; in < 4; in++)                                \
                    hmma(acc[im][in], a[im][0], a[im][1], a[im][2], a[im][3], \
                         bfr[in >> 1][(in & 1) * 2], bfr[in >> 1][(in & 1) * 2 + 1]); \
        }                                                                     \
    }

template <int EPI>
__global__ __launch_bounds__(256, 2)
void gemm_mma(const __half* __restrict__ A, const __half* __restrict__ Bt,
              const float* __restrict__ bias, const float* __restrict__ res,
              void* __restrict__ Cv, int N, int K)
{
    GEMM_PRE();
    GEMM_MAINLOOP();

    float*  Cf = (float*)Cv;
    __half* Ch = (__half*)Cv;
#pragma unroll
    for (int im = 0; im < 4; im++) {
        int r0 = bm + wm + im * 16 + lq;
#pragma unroll
        for (int in = 0; in < 4; in++) {
            int cc = bn + wn + in * 8 + c2;
            float b0 = 0.f, b1 = 0.f;
            if (bias) { b0 = bias[cc]; b1 = bias[cc + 1]; }
            float v0 = acc[im][in][0] + b0;
            float v1 = acc[im][in][1] + b1;
            float v2 = acc[im][in][2] + b0;
            float v3 = acc[im][in][3] + b1;
            if (EPI == 1) {
                v0 += res[(size_t)r0 * N + cc];
                v1 += res[(size_t)r0 * N + cc + 1];
                v2 += res[(size_t)(r0 + 8) * N + cc];
                v3 += res[(size_t)(r0 + 8) * N + cc + 1];
            }
            if (EPI == 2 || EPI == 3) {
                if (EPI == 2) {
                    v0 = fmaxf(v0, 0.f); v1 = fmaxf(v1, 0.f);
                    v2 = fmaxf(v2, 0.f); v3 = fmaxf(v3, 0.f);
                }
                *(__half2*)&Ch[(size_t)r0 * N + cc] =
                    __halves2half2(__float2half(v0), __float2half(v1));
                *(__half2*)&Ch[(size_t)(r0 + 8) * N + cc] =
                    __halves2half2(__float2half(v2), __float2half(v3));
            } else {
                *(float2*)&Cf[(size_t)r0 * N + cc] = make_float2(v0, v1);
                *(float2*)&Cf[(size_t)(r0 + 8) * N + cc] = make_float2(v2, v3);
            }
        }
    }
}

// ---------------------------------------------------------------------------
// LM-head GEMM, 128x256 CTA tile, 64x64 warp tiles, 1 CTA/SM.
// Fused logsumexp partials + target-logit capture (256-col slabs).
// ---------------------------------------------------------------------------
#define LM_TILEA (128 * BK * 2)        // 16 KB
#define LM_TILEB (256 * BK * 2)        // 32 KB
#define LM_STAGE (LM_TILEA + LM_TILEB) // 48 KB
#define GEMM_LM_SMEM (3 * LM_STAGE)    // 144 KB

#define LOAD_LM(T)                                                            \
    {                                                                         \
        uint32_t base_ = sA + ((T) % 3) * LM_STAGE;                           \
        int ko_ = (T) * BK;                                                   \
        _Pragma("unroll")                                                     \
        for (int p = 0; p < 4; p++)                                           \
            cpa16(base_ + ((ldr + p * 32) * BK) * 2 + swo,                    \
                  Ag + (size_t)(p * 32) * K + ko_);                           \
        _Pragma("unroll")                                                     \
        for (int p = 0; p < 8; p++)                                           \
            cpa16(base_ + LM_TILEA + ((ldr + p * 32) * BK) * 2 + swo,         \
                  Bg + (size_t)(p * 32) * K + ko_);                           \
        asm volatile("cp.async.commit_group;" ::: "memory");                  \
    }

__global__ __launch_bounds__(256, 1)
void gemm_lm(const __half* __restrict__ A, const __half* __restrict__ Bt,
             const float* __restrict__ bias, const int* __restrict__ targets,
             float2* __restrict__ part, float* __restrict__ zt, int K)
{
    extern __shared__ __half smh[];
    uint32_t sA = s2u(smh);
    const int tid = threadIdx.x;
    const int bn = blockIdx.x * 256;
    const int bm = blockIdx.y * 128;
    const int wid = tid >> 5, l = tid & 31;
    const int wm = (wid & 1) * 64;
    const int wn = (wid >> 1) * 64;
    const int nt = K / BK;
    const int c2 = (l & 3) * 2;
    const int lq = l >> 2;
    const int ldr = tid >> 3;
    const int ldc8 = tid & 7;
    const __half* Ag = A  + (size_t)(bm + ldr) * K + ldc8 * 8;
    const __half* Bg = Bt + (size_t)(bn + ldr) * K + ldc8 * 8;
    const uint32_t swo = ((ldc8 ^ (ldr & 7)) * 8) * 2;
    const int a_row  = l & 15;
    const int a_kch  = l >> 4;
    const int b_nrow = (l & 7) + ((l >> 4) << 3);
    const int b_kch  = (l >> 3) & 1;

    float acc[4][8][4];
#pragma unroll
    for (int i = 0; i < 4; i++)
#pragma unroll
        for (int j = 0; j < 8; j++)
#pragma unroll
            for (int c = 0; c < 4; c++) acc[i][j][c] = 0.f;

    LOAD_LM(0);
    if (nt > 1) LOAD_LM(1);
    for (int t = 0; t < nt; t++) {
        if (t + 1 < nt) { asm volatile("cp.async.wait_group 1;" ::: "memory"); }
        else            { asm volatile("cp.async.wait_group 0;" ::: "memory"); }
        __syncthreads();
        if (t + 2 < nt) LOAD_LM(t + 2);
        uint32_t Ab = sA + (t % 3) * LM_STAGE;
        uint32_t Bb = Ab + LM_TILEA;
#pragma unroll
        for (int kk = 0; kk < 4; kk++) {
            uint32_t a[4][4], bfr[4][4];
#pragma unroll
            for (int im = 0; im < 4; im++) {
                int row_ = wm + im * 16 + a_row;
                int ch_ = (kk * 2 + a_kch) ^ (row_ & 7);
                ldsm4(a[im], Ab + (row_ * BK + ch_ * 8) * 2);
            }
#pragma unroll
            for (int g = 0; g < 4; g++) {
                int row_ = wn + g * 16 + b_nrow;
                int ch_ = (kk * 2 + b_kch) ^ (row_ & 7);
                ldsm4(bfr[g], Bb + (row_ * BK + ch_ * 8) * 2);
            }
#pragma unroll
            for (int im = 0; im < 4; im++)
#pragma unroll
                for (int g = 0; g < 4; g++) {
                    hmma(acc[im][2 * g],     a[im][0], a[im][1], a[im][2], a[im][3],
                         bfr[g][0], bfr[g][1]);
                    hmma(acc[im][2 * g + 1], a[im][0], a[im][1], a[im][2], a[im][3],
                         bfr[g][2], bfr[g][3]);
                }
        }
    }

    // bias add + target capture
#pragma unroll
    for (int im = 0; im < 4; im++) {
        int r0g = bm + wm + im * 16 + lq;
        int r1g = r0g + 8;
        int t0 = targets[r0g], t1 = targets[r1g];
#pragma unroll
        for (int in = 0; in < 8; in++) {
            int cc = bn + wn + in * 8 + c2;
            float b0 = bias[cc], b1 = bias[cc + 1];
            acc[im][in][0] += b0; acc[im][in][1] += b1;
            acc[im][in][2] += b0; acc[im][in][3] += b1;
            if (cc     == t0) zt[r0g] = acc[im][in][0];
            if (cc + 1 == t0) zt[r0g] = acc[im][in][1];
            if (cc     == t1) zt[r1g] = acc[im][in][2];
            if (cc + 1 == t1) zt[r1g] = acc[im][in][3];
        }
    }

    float* redM = (float*)smh;             // [128][4]
    float* redS = redM + 512;
    __syncthreads();

#pragma unroll
    for (int im = 0; im < 4; im++)
#pragma unroll
        for (int h = 0; h < 2; h++) {
            float mx = -INFINITY;
#pragma unroll
            for (int in = 0; in < 8; in++)
                mx = fmaxf(mx, fmaxf(acc[im][in][h * 2], acc[im][in][h * 2 + 1]));
            mx = fmaxf(mx, __shfl_xor_sync(0xFFFFFFFF, mx, 1));
            mx = fmaxf(mx, __shfl_xor_sync(0xFFFFFFFF, mx, 2));
            int row = wm + im * 16 + lq + h * 8;
            if ((l & 3) == 0) redM[row * 4 + (wid >> 1)] = mx;
        }
    __syncthreads();

#pragma unroll
    for (int im = 0; im < 4; im++)
#pragma unroll
        for (int h = 0; h < 2; h++) {
            int row = wm + im * 16 + lq + h * 8;
            float rm = fmaxf(fmaxf(redM[row * 4 + 0], redM[row * 4 + 1]),
                             fmaxf(redM[row * 4 + 2], redM[row * 4 + 3]));
            float se = 0.f;
#pragma unroll
            for (int in = 0; in < 8; in++) {
                float d0 = acc[im][in][h * 2]     - rm;
                float d1 = acc[im][in][h * 2 + 1] - rm;
                if (in & 1) { se += exp_poly(d0); se += exp_poly(d1); }
                else        { se += __expf(d0);   se += __expf(d1);   }
            }
            se += __shfl_xor_sync(0xFFFFFFFF, se, 1);
            se += __shfl_xor_sync(0xFFFFFFFF, se, 2);
            if ((l & 3) == 0) redS[row * 4 + (wid >> 1)] = se;
        }
    __syncthreads();

    if (tid < 128) {
        float m = fmaxf(fmaxf(redM[tid * 4 + 0], redM[tid * 4 + 1]),
                        fmaxf(redM[tid * 4 + 2], redM[tid * 4 + 3]));
        float s = redS[tid * 4 + 0] + redS[tid * 4 + 1]
                + redS[tid * 4 + 2] + redS[tid * 4 + 3];
        part[(size_t)(bm + tid) * NSLAB + blockIdx.x] = make_float2(m, s);
    }
}

// ---------------------------------------------------------------------------
// HMMA attention: 32 q-rows x one (b,h) per CTA. ldmatrix everywhere;
// V consumed via ldmatrix.trans (no smem transpose).
// ---------------------------------------------------------------------------
#define SQ 32
#define SPITCH 1036                    // floats per S row (ldsm conflict-free)
#define KVP 72                         // halves per KV row
#define ATT_SMEM (SQ * SPITCH * 4 + 2 * 128 * KVP * 2 + SQ * KVP * 2)

#define LOAD_KV_TILE(DSTP, GOFF)                                              \
    {                                                                         \
        _Pragma("unroll")                                                     \
        for (int u_ = 0; u_ < 4; u_++) {                                      \
            int c_ = tid + 256 * u_;                                          \
            int tok_ = c_ >> 3, o8_ = (c_ & 7) * 8;                           \
            cpa16(s2u(DSTP) + (tok_ * KVP + o8_) * 2,                         \
                  qkvh + qbase + (GOFF) + (size_t)tok_ * 3072 + o8_);         \
        }                                                                     \
        asm volatile("cp.async.commit_group;" ::: "memory");                  \
    }

__global__ __launch_bounds__(256)
void attn_hmma(const __half* __restrict__ qkvh, float* __restrict__ attn,
               __half* __restrict__ oh)
{
    extern __shared__ float sm[];
    float*  S   = sm;                                  // [32][1036] f32
    __half* KV0 = (__half*)(sm + SQ * SPITCH);         // [128][72]
    __half* KV1 = KV0 + 128 * KVP;
    __half* Q   = KV1 + 128 * KVP;                     // [32][72]

    const int tid = threadIdx.x;
    const int q0 = blockIdx.x * SQ;
    const int bh = blockIdx.y;
    const int b = bh >> 4, hh = bh & 15;
    const int wid = tid >> 5, l = tid & 31;
    const int c2 = (l & 3) * 2;
    const int lq = l >> 2;
    const int l15 = l & 15;
    const int kh8 = (l >> 4) * 8;
    const int bn8 = (l & 7) + ((l >> 4) << 3);
    const int bk8 = ((l >> 3) & 1) * 8;
    const int ntile = (q0 >> 7) + 1;
    const int region = ntile << 7;
    const size_t qbase = (size_t)(b * SEQ) * 3072 + hh * 64;
    const uint32_t Qu = s2u(Q);
    const uint32_t Su = s2u(S);

    {
        int r = tid >> 3, c8 = (tid & 7) * 8;
        cpa16(Qu + (r * KVP + c8) * 2, qkvh + qbase + (size_t)(q0 + r) * 3072 + c8);
    }
    LOAD_KV_TILE(KV0, 1024);

    const int wm = (wid & 1) * 16;
    const int wn = (wid >> 1) * 32;

    // ---- scores ----
    for (int t = 0; t < ntile; t++) {
        if (t + 1 < ntile) {
            __half* KB = ((t + 1) & 1) ? KV1 : KV0;
            size_t goff = 1024 + (size_t)((t + 1) << 7) * 3072;
            LOAD_KV_TILE(KB, goff);
            asm volatile("cp.async.wait_group 1;" ::: "memory");
        } else {
            asm volatile("cp.async.wait_group 0;" ::: "memory");
        }
        __syncthreads();
        const uint32_t kbu = s2u((t & 1) ? KV1 : KV0);
        int kt0 = t << 7;
        float acc[4][4];
#pragma unroll
        for (int in = 0; in < 4; in++)
#pragma unroll
            for (int c = 0; c < 4; c++) acc[in][c] = 0.f;
#pragma unroll
        for (int kk = 0; kk < 4; kk++) {
            int k0 = kk * 16;
            uint32_t qa[4], kb0[4], kb1[4];
            ldsm4(qa,  Qu  + ((wm + l15) * KVP + k0 + kh8) * 2);
            ldsm4(kb0, kbu + ((wn + bn8) * KVP + k0 + bk8) * 2);
            ldsm4(kb1, kbu + ((wn + 16 + bn8) * KVP + k0 + bk8) * 2);
            hmma(acc[0], qa[0], qa[1], qa[2], qa[3], kb0[0], kb0[1]);
            hmma(acc[1], qa[0], qa[1], qa[2], qa[3], kb0[2], kb0[3]);
            hmma(acc[2], qa[0], qa[1], qa[2], qa[3], kb1[0], kb1[1]);
            hmma(acc[3], qa[0], qa[1], qa[2], qa[3], kb1[2], kb1[3]);
        }
        int qr = wm + lq;
#pragma unroll
        for (int in = 0; in < 4; in++) {
            int kg = kt0 + wn + in * 8 + c2;
            float v0 = (kg     <= q0 + qr)     ? acc[in][0] * 0.125f : -INFINITY;
            float v1 = (kg + 1 <= q0 + qr)     ? acc[in][1] * 0.125f : -INFINITY;
            float v2 = (kg     <= q0 + qr + 8) ? acc[in][2] * 0.125f : -INFINITY;
            float v3 = (kg + 1 <= q0 + qr + 8) ? acc[in][3] * 0.125f : -INFINITY;
            *(float2*)&S[qr * SPITCH + kg]       = make_float2(v0, v1);
            *(float2*)&S[(qr + 8) * SPITCH + kg] = make_float2(v2, v3);
        }
        __syncthreads();
    }

    // prefetch V tile 0 (overlaps softmax)
    LOAD_KV_TILE(KV0, 2048);

    // ---- softmax ----
    for (int rr = 0; rr < 4; rr++) {
        int q = wid * 4 + rr;
        int qt = q0 + q;
        float* Sr = S + q * SPITCH;
        float m = -INFINITY;
        for (int j = l; j <= qt; j += 32) m = fmaxf(m, Sr[j]);
#pragma unroll
        for (int st = 16; st > 0; st >>= 1)
            m = fmaxf(m, __shfl_xor_sync(0xFFFFFFFF, m, st));
        float ssum = 0.f;
        int it = 0;
        for (int j = l; j <= qt; j += 32, it++) {
            float d = Sr[j] - m;
            float e = (it & 1) ? exp_poly(d) : __expf(d);
            Sr[j] = e;
            ssum += e;
        }
#pragma unroll
        for (int st = 16; st > 0; st >>= 1)
            ssum += __shfl_xor_sync(0xFFFFFFFF, ssum, st);
        float inv = 1.0f / ssum;
        __half* Pr = (__half*)Sr;
        float* dst = attn + ((size_t)bh * SEQ + qt) * SEQ;
        for (int j = l; j < region; j += 32) {
            float p = (j <= qt) ? Sr[j] * inv : 0.f;
            dst[j] = p;
            Pr[j] = __float2half(p);
        }
        for (int j = region + l; j < SEQ; j += 32) dst[j] = 0.f;
    }
    __syncthreads();

    // ---- AV: P (ldsm on S-as-half) x V (ldsm.trans) ----
    const int wn2 = (wid >> 1) * 16;
    float oacc[2][4];
#pragma unroll
    for (int in = 0; in < 2; in++)
#pragma unroll
        for (int c = 0; c < 4; c++) oacc[in][c] = 0.f;

    for (int t = 0; t < ntile; t++) {
        if (t + 1 < ntile) {
            __half* KB = ((t + 1) & 1) ? KV1 : KV0;
            size_t goff = 2048 + (size_t)((t + 1) << 7) * 3072;
            LOAD_KV_TILE(KB, goff);
            asm volatile("cp.async.wait_group 1;" ::: "memory");
        } else {
            asm volatile("cp.async.wait_group 0;" ::: "memory");
        }
        __syncthreads();
        const uint32_t kbu = s2u((t & 1) ? KV1 : KV0);
        int kt0 = t << 7;
#pragma unroll
        for (int kk = 0; kk < 8; kk++) {
            int k0 = kk * 16;
            uint32_t pa[4], vb[4];
            ldsm4(pa, Su + ((wm + l15) * (SPITCH * 2) + kt0 + k0 + kh8) * 2);
            ldsm4t(vb, kbu + ((k0 + l15) * KVP + wn2 + kh8) * 2);
            hmma(oacc[0], pa[0], pa[1], pa[2], pa[3], vb[0], vb[1]);
            hmma(oacc[1], pa[0], pa[1], pa[2], pa[3], vb[2], vb[3]);
        }
        __syncthreads();
    }
#pragma unroll
    for (int in = 0; in < 2; in++) {
        int q = q0 + wm + lq;
        int s = wn2 + in * 8 + c2;
        *(__half2*)&oh[(size_t)(b * SEQ + q) * DIM + hh * 64 + s] =
            __halves2half2(__float2half(oacc[in][0]), __float2half(oacc[in][1]));
        *(__half2*)&oh[(size_t)(b * SEQ + q + 8) * DIM + hh * 64 + s] =
            __halves2half2(__float2half(oacc[in][2]), __float2half(oacc[in][3]));
    }
}
#undef LOAD_KV_TILE

// ---------------------------------------------------------------------------
// Merge per-slab (m,s) partials -> per-row loss
// ---------------------------------------------------------------------------
__global__ __launch_bounds__(256)
void loss_from_parts(const float2* __restrict__ part, const float* __restrict__ zt,
                     float* __restrict__ rowloss)
{
    int w = threadIdx.x >> 5, l = threadIdx.x & 31;
    int row = blockIdx.x * 8 + w;
    float m = -INFINITY, s = 0.f;
    for (int p = l; p < NSLAB; p += 32) {
        float2 ps = part[(size_t)row * NSLAB + p];
        float M = fmaxf(m, ps.x);
        s = s * __expf(m - M) + ps.y * __expf(ps.x - M);
        m = M;
    }
#pragma unroll
    for (int st = 16; st > 0; st >>= 1) {
        float m2 = __shfl_xor_sync(0xFFFFFFFF, m, st);
        float s2 = __shfl_xor_sync(0xFFFFFFFF, s, st);
        float M = fmaxf(m, m2);
        s = s * __expf(m - M) + s2 * __expf(m2 - M);
        m = M;
    }
    if (l == 0) rowloss[row] = m + logf(s) - zt[row];
}

__global__ void loss_reduce_kernel(const float* __restrict__ rowloss, float* __restrict__ out)
{
    __shared__ float red[256];
    int tid = threadIdx.x;
    float s = 0.f;
    for (int i = tid; i < ROWS; i += 256) s += rowloss[i];
    red[tid] = s;
    __syncthreads();
    for (int st = 128; st > 0; st >>= 1) {
        if (tid < st) red[tid] += red[tid + st];
        __syncthreads();
    }
    if (tid == 0) out[0] = red[0] * (1.0f / ROWS);
}

// ---------------------------------------------------------------------------
// Host
// ---------------------------------------------------------------------------
extern "C" void kernel_launch(void* const* d_in, const int* in_sizes, int n_in,
                              void* d_out, int out_size)
{
    const int*   idx     = (const int*)  d_in[0];
    const int*   targets = (const int*)  d_in[1];
    const float* tok_emb = (const float*)d_in[2];
    const float* pos_emb = (const float*)d_in[3];
    const float* ln1_g   = (const float*)d_in[4];
    const float* ln1_b   = (const float*)d_in[5];
    const float* Wq      = (const float*)d_in[6];
    const float* Wk      = (const float*)d_in[7];
    const float* Wv      = (const float*)d_in[8];
    const float* Wp      = (const float*)d_in[9];
    const float* bp      = (const float*)d_in[10];
    const float* ln2_g   = (const float*)d_in[11];
    const float* ln2_b   = (const float*)d_in[12];
    const float* W1      = (const float*)d_in[13];
    const float* b1      = (const float*)d_in[14];
    const float* W2      = (const float*)d_in[15];
    const float* b2      = (const float*)d_in[16];
    const float* lnf_g   = (const float*)d_in[17];
    const float* lnf_b   = (const float*)d_in[18];
    const float* Wlm     = (const float*)d_in[19];
    const float* blm     = (const float*)d_in[20];

    float* out      = (float*)d_out;
    float* attn_out = out + 1;

    float *x, *rl, *ztp;
    float2* part;
    __half *hbuf, *qkvh, *ohb, *ffh, *wth;
    cudaGetSymbolAddress((void**)&x,    g_x);
    cudaGetSymbolAddress((void**)&hbuf, g_hh);
    cudaGetSymbolAddress((void**)&qkvh, g_qkvh);
    cudaGetSymbolAddress((void**)&ohb,  g_oh);
    cudaGetSymbolAddress((void**)&ffh,  g_ffh);
    cudaGetSymbolAddress((void**)&wth,  g_wth);
    cudaGetSymbolAddress((void**)&part, g_part);
    cudaGetSymbolAddress((void**)&ztp,  g_zt);
    cudaGetSymbolAddress((void**)&rl,   g_rl);

    cudaFuncSetAttribute(gemm_mma<0>, cudaFuncAttributeMaxDynamicSharedMemorySize, GEMM_SMEM);
    cudaFuncSetAttribute(gemm_mma<1>, cudaFuncAttributeMaxDynamicSharedMemorySize, GEMM_SMEM);
    cudaFuncSetAttribute(gemm_mma<2>, cudaFuncAttributeMaxDynamicSharedMemorySize, GEMM_SMEM);
    cudaFuncSetAttribute(gemm_mma<3>, cudaFuncAttributeMaxDynamicSharedMemorySize, GEMM_SMEM);
    cudaFuncSetAttribute(gemm_lm,     cudaFuncAttributeMaxDynamicSharedMemorySize, GEMM_LM_SMEM);
    cudaFuncSetAttribute(attn_hmma,   cudaFuncAttributeMaxDynamicSharedMemorySize, ATT_SMEM);

    embed_kernel<<<ROWS, 256>>>(idx, tok_emb, pos_emb, x);

    for (int l = 0; l < NL; l++) {
        ln_kernel<<<ROWS / 8, 256>>>(x, ln1_g + (size_t)l * DIM, ln1_b + (size_t)l * DIM, hbuf);
        pack_qkv_t<<<dim3(HS / 32, DIM / 32, 3 * NH), dim3(32, 8)>>>(Wq, Wk, Wv, wth, l);
        gemm_mma<3><<<dim3(3 * DIM / 128, ROWS / 128), 256, GEMM_SMEM>>>(
            hbuf, wth, nullptr, nullptr, qkvh, 3 * DIM, DIM);

        float* attnL = attn_out + (size_t)l * BATCH * NH * SEQ * SEQ;
        attn_hmma<<<dim3(SEQ / SQ, BATCH * NH), 256, ATT_SMEM>>>(qkvh, attnL, ohb);

        transpose_k<<<dim3(DIM / 32, DIM / 32), dim3(32, 8)>>>(
            Wp + (size_t)l * DIM * DIM, wth, DIM, DIM);
        gemm_mma<1><<<dim3(DIM / 128, ROWS / 128), 256, GEMM_SMEM>>>(
            ohb, wth, bp + (size_t)l * DIM, x, x, DIM, DIM);

        ln_kernel<<<ROWS / 8, 256>>>(x, ln2_g + (size_t)l * DIM, ln2_b + (size_t)l * DIM, hbuf);

        transpose_k<<<dim3(FFD / 32, DIM / 32), dim3(32, 8)>>>(
            W1 + (size_t)l * DIM * FFD, wth, DIM, FFD);
        gemm_mma<2><<<dim3(FFD / 128, ROWS / 128), 256, GEMM_SMEM>>>(
            hbuf, wth, b1 + (size_t)l * FFD, nullptr, ffh, FFD, DIM);

        transpose_k<<<dim3(DIM / 32, FFD / 32), dim3(32, 8)>>>(
            W2 + (size_t)l * FFD * DIM, wth, FFD, DIM);
        gemm_mma<1><<<dim3(DIM / 128, ROWS / 128), 256, GEMM_SMEM>>>(
            ffh, wth, b2 + (size_t)l * DIM, x, x, DIM, FFD);
    }

    ln_kernel<<<ROWS / 8, 256>>>(x, lnf_g, lnf_b, hbuf);
    transpose_k<<<dim3(VOCAB / 32, DIM / 32), dim3(32, 8)>>>(Wlm, wth, DIM, VOCAB);
    gemm_lm<<<dim3(VOCAB / 256, ROWS / 128), 256, GEMM_LM_SMEM>>>(
        hbuf, wth, blm, targets, part, ztp, DIM);

    loss_from_parts<<<ROWS / 8, 256>>>(part, ztp, rl);
    loss_reduce_kernel<<<1, 256>>>(rl, out);
}

// round 16
// speedup vs baseline: 1.0457x; 1.0457x over previous
#include <cuda_runtime.h>
#include <cuda_fp16.h>
#include <math.h>
#include <stdint.h>

#define BATCH 4
#define SEQ   1024
#define DIM   1024
#define NH    16
#define HS    64
#define NL    4
#define FFD   4096
#define VOCAB 32000
#define ROWS  (BATCH * SEQ)
#define NSLAB (VOCAB / 128)            // 250

// ---------------------------------------------------------------------------
// Scratch
// ---------------------------------------------------------------------------
__device__ float  g_x   [(size_t)ROWS * DIM];        // residual (fp32)
__device__ __half g_hh  [(size_t)ROWS * DIM];        // LN output (fp16)
__device__ __half g_qkvh[(size_t)ROWS * 3 * DIM];    // q|k|v per row (fp16)
__device__ __half g_oh  [(size_t)ROWS * DIM];        // attn output (fp16)
__device__ __half g_ffh [(size_t)ROWS * FFD];        // MLP hidden (fp16)
__device__ __half g_wth [(size_t)VOCAB * DIM];       // transposed weights (fp16)
__device__ float2 g_part[(size_t)ROWS * NSLAB];      // per-slab (max, sumexp)
__device__ float  g_zt  [ROWS];                      // target logits
__device__ float  g_rl  [ROWS];

// ---------------------------------------------------------------------------
// Helpers
// ---------------------------------------------------------------------------
__device__ __forceinline__ uint32_t s2u(const void* p) {
    uint32_t a;
    asm("{ .reg .u64 t; cvta.to.shared.u64 t, %1; cvt.u32.u64 %0, t; }" : "=r"(a) : "l"(p));
    return a;
}
__device__ __forceinline__ void cpa16(uint32_t dst, const void* src) {
    asm volatile("cp.async.cg.shared.global [%0], [%1], 16;" :: "r"(dst), "l"(src));
}
__device__ __forceinline__ void hmma(float* c, uint32_t a0, uint32_t a1, uint32_t a2,
                                     uint32_t a3, uint32_t b0, uint32_t b1) {
    asm volatile(
        "mma.sync.aligned.m16n8k16.row.col.f32.f16.f16.f32 "
        "{%0,%1,%2,%3}, {%4,%5,%6,%7}, {%8,%9}, {%0,%1,%2,%3};"
        : "+f"(c[0]), "+f"(c[1]), "+f"(c[2]), "+f"(c[3])
        : "r"(a0), "r"(a1), "r"(a2), "r"(a3), "r"(b0), "r"(b1));
}
__device__ __forceinline__ void ldsm4(uint32_t* d, uint32_t addr) {
    asm volatile("ldmatrix.sync.aligned.m8n8.x4.shared.b16 {%0,%1,%2,%3}, [%4];"
                 : "=r"(d[0]), "=r"(d[1]), "=r"(d[2]), "=r"(d[3]) : "r"(addr));
}
__device__ __forceinline__ void ldsm4t(uint32_t* d, uint32_t addr) {
    asm volatile("ldmatrix.sync.aligned.m8n8.x4.trans.shared.b16 {%0,%1,%2,%3}, [%4];"
                 : "=r"(d[0]), "=r"(d[1]), "=r"(d[2]), "=r"(d[3]) : "r"(addr));
}
// e^x for x <= 0, FFMA/ALU-pipe polynomial (relieves MUFU)
__device__ __forceinline__ float exp_poly(float x) {
    float z = x * 1.4426950408889634f;
    float t = z + 12582912.0f;
    float n = t - 12582912.0f;
    float f = z - n;
    float p = 1.3333558e-3f;
    p = fmaf(p, f, 9.6181291e-3f);
    p = fmaf(p, f, 5.5504109e-2f);
    p = fmaf(p, f, 2.4022651e-1f);
    p = fmaf(p, f, 6.9314718e-1f);
    p = fmaf(p, f, 1.0f);
    float sc = __int_as_float((((int)n) + 127) << 23);
    return (x < -80.f) ? 0.f : p * sc;
}

// ---------------------------------------------------------------------------
// Embedding
// ---------------------------------------------------------------------------
__global__ void embed_kernel(const int* __restrict__ idx,
                             const float* __restrict__ tok,
                             const float* __restrict__ pos,
                             float* __restrict__ x)
{
    int row = blockIdx.x;
    int t   = row & (SEQ - 1);
    int tk  = idx[row];
    const float* te = tok + (size_t)tk * DIM;
    const float* pe = pos + (size_t)t * DIM;
    float* xr = x + (size_t)row * DIM;
    for (int i = threadIdx.x; i < DIM; i += blockDim.x)
        xr[i] = te[i] + pe[i];
}

// ---------------------------------------------------------------------------
// LayerNorm -> fp16, warp-per-row (8 rows per 256-thread CTA)
// ---------------------------------------------------------------------------
__global__ __launch_bounds__(256)
void ln_kernel(const float* __restrict__ x,
               const float* __restrict__ g,
               const float* __restrict__ b,
               __half* __restrict__ y)
{
    int w = threadIdx.x >> 5, l = threadIdx.x & 31;
    int row = blockIdx.x * 8 + w;
    const float4* xr = (const float4*)(x + (size_t)row * DIM);
    float4 v[8];
    float s = 0.f, ss = 0.f;
#pragma unroll
    for (int j = 0; j < 8; j++) {
        v[j] = xr[l + 32 * j];
        s  += v[j].x + v[j].y + v[j].z + v[j].w;
        ss += v[j].x * v[j].x + v[j].y * v[j].y + v[j].z * v[j].z + v[j].w * v[j].w;
    }
#pragma unroll
    for (int st = 16; st > 0; st >>= 1) {
        s  += __shfl_xor_sync(0xFFFFFFFF, s, st);
        ss += __shfl_xor_sync(0xFFFFFFFF, ss, st);
    }
    float mean = s * (1.0f / DIM);
    float var  = fmaxf(ss * (1.0f / DIM) - mean * mean, 0.f);
    float rstd = rsqrtf(var + 1e-5f);
    const float4* g4 = (const float4*)g;
    const float4* b4 = (const float4*)b;
    __half2* yr = (__half2*)(y + (size_t)row * DIM);
#pragma unroll
    for (int j = 0; j < 8; j++) {
        int i4 = l + 32 * j;
        float4 gg = g4[i4], bb = b4[i4];
        float o0 = (v[j].x - mean) * rstd * gg.x + bb.x;
        float o1 = (v[j].y - mean) * rstd * gg.y + bb.y;
        float o2 = (v[j].z - mean) * rstd * gg.z + bb.z;
        float o3 = (v[j].w - mean) * rstd * gg.w + bb.w;
        yr[i4 * 2]     = __halves2half2(__float2half(o0), __float2half(o1));
        yr[i4 * 2 + 1] = __halves2half2(__float2half(o2), __float2half(o3));
    }
}

// ---------------------------------------------------------------------------
// Pack Wq|Wk|Wv -> [3*DIM][DIM] K-major fp16, coalesced via smem tile.
// ---------------------------------------------------------------------------
__global__ void pack_qkv_t(const float* __restrict__ Wq,
                           const float* __restrict__ Wk,
                           const float* __restrict__ Wv,
                           __half* __restrict__ out, int l)
{
    __shared__ float t[32][33];
    int z = blockIdx.z;                    // which*16 + h
    int which = z >> 4, h = z & 15;
    int s0 = blockIdx.x * 32, d0 = blockIdx.y * 32;
    int x = threadIdx.x, y = threadIdx.y;
    const float* W = (which == 0) ? Wq : (which == 1) ? Wk : Wv;
    const float* base = W + ((size_t)l * NH + h) * DIM * HS;     // [DIM][HS]
#pragma unroll
    for (int j = 0; j < 4; j++)
        t[y + 8 * j][x] = base[(size_t)(d0 + y + 8 * j) * HS + s0 + x];
    __syncthreads();
    __half* o = out + (size_t)(which * 1024 + h * 64) * DIM;
#pragma unroll
    for (int j = 0; j < 4; j++)
        o[(size_t)(s0 + y + 8 * j) * DIM + d0 + x] = __float2half(t[x][y + 8 * j]);
}

// ---------------------------------------------------------------------------
// Transpose [R][C] fp32 -> [C][R] fp16
// ---------------------------------------------------------------------------
__global__ void transpose_k(const float* __restrict__ in, __half* __restrict__ out,
                            int R, int C)
{
    __shared__ float t[32][33];
    int c0 = blockIdx.x * 32, r0 = blockIdx.y * 32;
    int x = threadIdx.x, y = threadIdx.y;
#pragma unroll
    for (int j = 0; j < 4; j++)
        t[y + 8 * j][x] = in[(size_t)(r0 + y + 8 * j) * C + c0 + x];
    __syncthreads();
#pragma unroll
    for (int j = 0; j < 4; j++)
        out[(size_t)(c0 + y + 8 * j) * R + r0 + x] = __float2half(t[x][y + 8 * j]);
}

// ---------------------------------------------------------------------------
// fp16 HMMA GEMM: 128x128 CTA tile, 4 warps of 64x64, 128 threads,
// BK=64 XOR-swizzled smem, ldmatrix, 3-stage cp.async pipeline, 2 CTAs/SM.
// ---------------------------------------------------------------------------
#define BK 64
#define TILEB (128 * BK * 2)           // 16384 B per operand tile
#define GEMM_SMEM (6 * TILEB)          // 3 stages x (A,B) = 96 KB

#define GEMM_PRE()                                                            \
    extern __shared__ __half smh[];                                           \
    uint32_t sA = s2u(smh);                                                   \
    uint32_t sB = sA + 3 * TILEB;                                             \
    const int tid = threadIdx.x;                                              \
    const int bn = blockIdx.x * 128;                                          \
    const int bm = blockIdx.y * 128;                                          \
    const int wid = tid >> 5, l = tid & 31;                                   \
    const int wm = (wid & 1) * 64;                                            \
    const int wn = (wid >> 1) * 64;                                           \
    const int nt = K / BK;                                                    \
    const int c2 = (l & 3) * 2;                                               \
    const int lq = l >> 2;                                                    \
    const int ldr = tid >> 3;              /* 0..15 */                        \
    const int ldc8 = tid & 7;              /* chunk col */                    \
    const __half* Ag = A  + (size_t)(bm + ldr) * K + ldc8 * 8;                \
    const __half* Bg = Bt + (size_t)(bn + ldr) * K + ldc8 * 8;                \
    const uint32_t sAo = sA + (ldr * BK + ((ldc8 ^ (ldr & 7)) * 8)) * 2;      \
    const uint32_t sBo = sB + (ldr * BK + ((ldc8 ^ (ldr & 7)) * 8)) * 2;      \
    float acc[4][8][4];                                                       \
    _Pragma("unroll")                                                         \
    for (int i = 0; i < 4; i++)                                               \
        _Pragma("unroll")                                                     \
        for (int j = 0; j < 8; j++)                                           \
            _Pragma("unroll")                                                 \
            for (int c = 0; c < 4; c++) acc[i][j][c] = 0.f;                   \
    const int a_row  = l & 15;                                                \
    const int a_kch  = l >> 4;                                                \
    const int b_nrow = (l & 7) + ((l >> 4) << 3);                             \
    const int b_kch  = (l >> 3) & 1;

#define LOAD_TILE(T)                                                          \
    {                                                                         \
        int buf_ = (T) % 3;                                                   \
        int ko_ = (T) * BK;                                                   \
        _Pragma("unroll")                                                     \
        for (int p = 0; p < 8; p++) {                                         \
            cpa16(sAo + buf_ * TILEB + p * 16 * BK * 2,                       \
                  Ag + (size_t)(p * 16) * K + ko_);                           \
            cpa16(sBo + buf_ * TILEB + p * 16 * BK * 2,                       \
                  Bg + (size_t)(p * 16) * K + ko_);                           \
        }                                                                     \
        asm volatile("cp.async.commit_group;" ::: "memory");                  \
    }

#define GEMM_MAINLOOP()                                                       \
    LOAD_TILE(0);                                                             \
    if (nt > 1) LOAD_TILE(1);                                                 \
    for (int t = 0; t < nt; t++) {                                            \
        if (t + 1 < nt) { asm volatile("cp.async.wait_group 1;" ::: "memory"); } \
        else            { asm volatile("cp.async.wait_group 0;" ::: "memory"); } \
        __syncthreads();                                                      \
        if (t + 2 < nt) LOAD_TILE(t + 2);                                     \
        uint32_t Ab = sA + (t % 3) * TILEB;                                   \
        uint32_t Bb = sB + (t % 3) * TILEB;                                   \
        _Pragma("unroll")                                                     \
        for (int kk = 0; kk < 4; kk++) {                                      \
            uint32_t a[4][4], bfr[4][4];                                      \
            _Pragma("unroll")                                                 \
            for (int im = 0; im < 4; im++) {                                  \
                int row_ = wm + im * 16 + a_row;                              \
                int ch_ = (kk * 2 + a_kch) ^ (row_ & 7);                      \
                ldsm4(a[im], Ab + (row_ * BK + ch_ * 8) * 2);                 \
            }                                                                 \
            _Pragma("unroll")                                                 \
            for (int g = 0; g < 4; g++) {                                     \
                int row_ = wn + g * 16 + b_nrow;                              \
                int ch_ = (kk * 2 + b_kch) ^ (row_ & 7);                      \
                ldsm4(bfr[g], Bb + (row_ * BK + ch_ * 8) * 2);                \
            }                                                                 \
            _Pragma("unroll")                                                 \
            for (int im = 0; im < 4; im++)                                    \
                _Pragma("unroll")                                             \
                for (int in = 0; in < 8; in++)                                \
                    hmma(acc[im][in], a[im][0], a[im][1], a[im][2], a[im][3], \
                         bfr[in >> 1][(in & 1) * 2], bfr[in >> 1][(in & 1) * 2 + 1]); \
        }                                                                     \
    }

template <int EPI>
__global__ __launch_bounds__(128, 2)
void gemm_mma(const __half* __restrict__ A, const __half* __restrict__ Bt,
              const float* __restrict__ bias, const float* __restrict__ res,
              void* __restrict__ Cv, int N, int K)
{
    GEMM_PRE();
    GEMM_MAINLOOP();

    float*  Cf = (float*)Cv;
    __half* Ch = (__half*)Cv;
#pragma unroll
    for (int im = 0; im < 4; im++) {
        int r0 = bm + wm + im * 16 + lq;
#pragma unroll
        for (int in = 0; in < 8; in++) {
            int cc = bn + wn + in * 8 + c2;
            float b0 = 0.f, b1 = 0.f;
            if (bias) { b0 = bias[cc]; b1 = bias[cc + 1]; }
            float v0 = acc[im][in][0] + b0;
            float v1 = acc[im][in][1] + b1;
            float v2 = acc[im][in][2] + b0;
            float v3 = acc[im][in][3] + b1;
            if (EPI == 1) {
                v0 += res[(size_t)r0 * N + cc];
                v1 += res[(size_t)r0 * N + cc + 1];
                v2 += res[(size_t)(r0 + 8) * N + cc];
                v3 += res[(size_t)(r0 + 8) * N + cc + 1];
            }
            if (EPI == 2 || EPI == 3) {
                if (EPI == 2) {
                    v0 = fmaxf(v0, 0.f); v1 = fmaxf(v1, 0.f);
                    v2 = fmaxf(v2, 0.f); v3 = fmaxf(v3, 0.f);
                }
                *(__half2*)&Ch[(size_t)r0 * N + cc] =
                    __halves2half2(__float2half(v0), __float2half(v1));
                *(__half2*)&Ch[(size_t)(r0 + 8) * N + cc] =
                    __halves2half2(__float2half(v2), __float2half(v3));
            } else {
                *(float2*)&Cf[(size_t)r0 * N + cc] = make_float2(v0, v1);
                *(float2*)&Cf[(size_t)(r0 + 8) * N + cc] = make_float2(v2, v3);
            }
        }
    }
}

// ---------------------------------------------------------------------------
// LM-head GEMM (same 4-warp core) with fused logsumexp partials + target
// logit capture. CTA covers 128 cols; two col-groups (wn 0/64) per row.
// ---------------------------------------------------------------------------
__global__ __launch_bounds__(128, 2)
void gemm_lm(const __half* __restrict__ A, const __half* __restrict__ Bt,
             const float* __restrict__ bias, const int* __restrict__ targets,
             float2* __restrict__ part, float* __restrict__ zt, int K)
{
    GEMM_PRE();
    GEMM_MAINLOOP();

#pragma unroll
    for (int im = 0; im < 4; im++) {
        int r0g = bm + wm + im * 16 + lq;
        int r1g = r0g + 8;
        int t0 = targets[r0g], t1 = targets[r1g];
#pragma unroll
        for (int in = 0; in < 8; in++) {
            int cc = bn + wn + in * 8 + c2;
            float b0 = bias[cc], b1 = bias[cc + 1];
            acc[im][in][0] += b0; acc[im][in][1] += b1;
            acc[im][in][2] += b0; acc[im][in][3] += b1;
            if (cc     == t0) zt[r0g] = acc[im][in][0];
            if (cc + 1 == t0) zt[r0g] = acc[im][in][1];
            if (cc     == t1) zt[r1g] = acc[im][in][2];
            if (cc + 1 == t1) zt[r1g] = acc[im][in][3];
        }
    }

    float* redM = (float*)smh;             // [128][2]
    float* redS = redM + 256;              // [128][2]
    __syncthreads();

#pragma unroll
    for (int im = 0; im < 4; im++)
#pragma unroll
        for (int h = 0; h < 2; h++) {
            float mx = -INFINITY;
#pragma unroll
            for (int in = 0; in < 8; in++)
                mx = fmaxf(mx, fmaxf(acc[im][in][h * 2], acc[im][in][h * 2 + 1]));
            mx = fmaxf(mx, __shfl_xor_sync(0xFFFFFFFF, mx, 1));
            mx = fmaxf(mx, __shfl_xor_sync(0xFFFFFFFF, mx, 2));
            int row = wm + im * 16 + lq + h * 8;
            if ((l & 3) == 0) redM[row * 2 + (wid >> 1)] = mx;
        }
    __syncthreads();

#pragma unroll
    for (int im = 0; im < 4; im++)
#pragma unroll
        for (int h = 0; h < 2; h++) {
            int row = wm + im * 16 + lq + h * 8;
            float rm = fmaxf(redM[row * 2 + 0], redM[row * 2 + 1]);
            float se = 0.f;
#pragma unroll
            for (int in = 0; in < 8; in++) {
                float d0 = acc[im][in][h * 2]     - rm;
                float d1 = acc[im][in][h * 2 + 1] - rm;
                if (in & 1) { se += exp_poly(d0); se += exp_poly(d1); }
                else        { se += __expf(d0);   se += __expf(d1);   }
            }
            se += __shfl_xor_sync(0xFFFFFFFF, se, 1);
            se += __shfl_xor_sync(0xFFFFFFFF, se, 2);
            if ((l & 3) == 0) redS[row * 2 + (wid >> 1)] = se;
        }
    __syncthreads();

    if (tid < 128) {
        float m = fmaxf(redM[tid * 2 + 0], redM[tid * 2 + 1]);
        float s = redS[tid * 2 + 0] + redS[tid * 2 + 1];
        part[(size_t)(bm + tid) * NSLAB + blockIdx.x] = make_float2(m, s);
    }
}

// ---------------------------------------------------------------------------
// HMMA attention: 32 q-rows x one (b,h) per CTA. ldmatrix everywhere;
// V consumed via ldmatrix.trans (no smem transpose). (R11-proven)
// ---------------------------------------------------------------------------
#define SQ 32
#define SPITCH 1036                    // floats per S row (ldsm conflict-free)
#define KVP 72                         // halves per KV row
#define ATT_SMEM (SQ * SPITCH * 4 + 2 * 128 * KVP * 2 + SQ * KVP * 2)

#define LOAD_KV_TILE(DSTP, GOFF)                                              \
    {                                                                         \
        _Pragma("unroll")                                                     \
        for (int u_ = 0; u_ < 4; u_++) {                                      \
            int c_ = tid + 256 * u_;                                          \
            int tok_ = c_ >> 3, o8_ = (c_ & 7) * 8;                           \
            cpa16(s2u(DSTP) + (tok_ * KVP + o8_) * 2,                         \
                  qkvh + qbase + (GOFF) + (size_t)tok_ * 3072 + o8_);         \
        }                                                                     \
        asm volatile("cp.async.commit_group;" ::: "memory");                  \
    }

__global__ __launch_bounds__(256)
void attn_hmma(const __half* __restrict__ qkvh, float* __restrict__ attn,
               __half* __restrict__ oh)
{
    extern __shared__ float sm[];
    float*  S   = sm;                                  // [32][1036] f32
    __half* KV0 = (__half*)(sm + SQ * SPITCH);         // [128][72]
    __half* KV1 = KV0 + 128 * KVP;
    __half* Q   = KV1 + 128 * KVP;                     // [32][72]

    const int tid = threadIdx.x;
    const int q0 = blockIdx.x * SQ;
    const int bh = blockIdx.y;
    const int b = bh >> 4, hh = bh & 15;
    const int wid = tid >> 5, l = tid & 31;
    const int c2 = (l & 3) * 2;
    const int lq = l >> 2;
    const int l15 = l & 15;
    const int kh8 = (l >> 4) * 8;
    const int bn8 = (l & 7) + ((l >> 4) << 3);
    const int bk8 = ((l >> 3) & 1) * 8;
    const int ntile = (q0 >> 7) + 1;
    const int region = ntile << 7;
    const size_t qbase = (size_t)(b * SEQ) * 3072 + hh * 64;
    const uint32_t Qu = s2u(Q);
    const uint32_t Su = s2u(S);

    {
        int r = tid >> 3, c8 = (tid & 7) * 8;
        cpa16(Qu + (r * KVP + c8) * 2, qkvh + qbase + (size_t)(q0 + r) * 3072 + c8);
    }
    LOAD_KV_TILE(KV0, 1024);

    const int wm = (wid & 1) * 16;
    const int wn = (wid >> 1) * 32;

    // ---- scores ----
    for (int t = 0; t < ntile; t++) {
        if (t + 1 < ntile) {
            __half* KB = ((t + 1) & 1) ? KV1 : KV0;
            size_t goff = 1024 + (size_t)((t + 1) << 7) * 3072;
            LOAD_KV_TILE(KB, goff);
            asm volatile("cp.async.wait_group 1;" ::: "memory");
        } else {
            asm volatile("cp.async.wait_group 0;" ::: "memory");
        }
        __syncthreads();
        const uint32_t kbu = s2u((t & 1) ? KV1 : KV0);
        int kt0 = t << 7;
        float acc[4][4];
#pragma unroll
        for (int in = 0; in < 4; in++)
#pragma unroll
            for (int c = 0; c < 4; c++) acc[in][c] = 0.f;
#pragma unroll
        for (int kk = 0; kk < 4; kk++) {
            int k0 = kk * 16;
            uint32_t qa[4], kb0[4], kb1[4];
            ldsm4(qa,  Qu  + ((wm + l15) * KVP + k0 + kh8) * 2);
            ldsm4(kb0, kbu + ((wn + bn8) * KVP + k0 + bk8) * 2);
            ldsm4(kb1, kbu + ((wn + 16 + bn8) * KVP + k0 + bk8) * 2);
            hmma(acc[0], qa[0], qa[1], qa[2], qa[3], kb0[0], kb0[1]);
            hmma(acc[1], qa[0], qa[1], qa[2], qa[3], kb0[2], kb0[3]);
            hmma(acc[2], qa[0], qa[1], qa[2], qa[3], kb1[0], kb1[1]);
            hmma(acc[3], qa[0], qa[1], qa[2], qa[3], kb1[2], kb1[3]);
        }
        int qr = wm + lq;
#pragma unroll
        for (int in = 0; in < 4; in++) {
            int kg = kt0 + wn + in * 8 + c2;
            float v0 = (kg     <= q0 + qr)     ? acc[in][0] * 0.125f : -INFINITY;
            float v1 = (kg + 1 <= q0 + qr)     ? acc[in][1] * 0.125f : -INFINITY;
            float v2 = (kg     <= q0 + qr + 8) ? acc[in][2] * 0.125f : -INFINITY;
            float v3 = (kg + 1 <= q0 + qr + 8) ? acc[in][3] * 0.125f : -INFINITY;
            *(float2*)&S[qr * SPITCH + kg]       = make_float2(v0, v1);
            *(float2*)&S[(qr + 8) * SPITCH + kg] = make_float2(v2, v3);
        }
        __syncthreads();
    }

    // prefetch V tile 0 (overlaps softmax)
    LOAD_KV_TILE(KV0, 2048);

    // ---- softmax ----
    for (int rr = 0; rr < 4; rr++) {
        int q = wid * 4 + rr;
        int qt = q0 + q;
        float* Sr = S + q * SPITCH;
        float m = -INFINITY;
        for (int j = l; j <= qt; j += 32) m = fmaxf(m, Sr[j]);
#pragma unroll
        for (int st = 16; st > 0; st >>= 1)
            m = fmaxf(m, __shfl_xor_sync(0xFFFFFFFF, m, st));
        float ssum = 0.f;
        int it = 0;
        for (int j = l; j <= qt; j += 32, it++) {
            float d = Sr[j] - m;
            float e = (it & 1) ? exp_poly(d) : __expf(d);
            Sr[j] = e;
            ssum += e;
        }
#pragma unroll
        for (int st = 16; st > 0; st >>= 1)
            ssum += __shfl_xor_sync(0xFFFFFFFF, ssum, st);
        float inv = 1.0f / ssum;
        __half* Pr = (__half*)Sr;
        float* dst = attn + ((size_t)bh * SEQ + qt) * SEQ;
        for (int j = l; j < region; j += 32) {
            float p = (j <= qt) ? Sr[j] * inv : 0.f;
            dst[j] = p;
            Pr[j] = __float2half(p);
        }
        for (int j = region + l; j < SEQ; j += 32) dst[j] = 0.f;
    }
    __syncthreads();

    // ---- AV: P (ldsm on S-as-half) x V (ldsm.trans) ----
    const int wn2 = (wid >> 1) * 16;
    float oacc[2][4];
#pragma unroll
    for (int in = 0; in < 2; in++)
#pragma unroll
        for (int c = 0; c < 4; c++) oacc[in][c] = 0.f;

    for (int t = 0; t < ntile; t++) {
        if (t + 1 < ntile) {
            __half* KB = ((t + 1) & 1) ? KV1 : KV0;
            size_t goff = 2048 + (size_t)((t + 1) << 7) * 3072;
            LOAD_KV_TILE(KB, goff);
            asm volatile("cp.async.wait_group 1;" ::: "memory");
        } else {
            asm volatile("cp.async.wait_group 0;" ::: "memory");
        }
        __syncthreads();
        const uint32_t kbu = s2u((t & 1) ? KV1 : KV0);
        int kt0 = t << 7;
#pragma unroll
        for (int kk = 0; kk < 8; kk++) {
            int k0 = kk * 16;
            uint32_t pa[4], vb[4];
            ldsm4(pa, Su + ((wm + l15) * (SPITCH * 2) + kt0 + k0 + kh8) * 2);
            ldsm4t(vb, kbu + ((k0 + l15) * KVP + wn2 + kh8) * 2);
            hmma(oacc[0], pa[0], pa[1], pa[2], pa[3], vb[0], vb[1]);
            hmma(oacc[1], pa[0], pa[1], pa[2], pa[3], vb[2], vb[3]);
        }
        __syncthreads();
    }
#pragma unroll
    for (int in = 0; in < 2; in++) {
        int q = q0 + wm + lq;
        int s = wn2 + in * 8 + c2;
        *(__half2*)&oh[(size_t)(b * SEQ + q) * DIM + hh * 64 + s] =
            __halves2half2(__float2half(oacc[in][0]), __float2half(oacc[in][1]));
        *(__half2*)&oh[(size_t)(b * SEQ + q + 8) * DIM + hh * 64 + s] =
            __halves2half2(__float2half(oacc[in][2]), __float2half(oacc[in][3]));
    }
}
#undef LOAD_KV_TILE

// ---------------------------------------------------------------------------
// Merge per-slab (m,s) partials -> per-row loss
// ---------------------------------------------------------------------------
__global__ __launch_bounds__(256)
void loss_from_parts(const float2* __restrict__ part, const float* __restrict__ zt,
                     float* __restrict__ rowloss)
{
    int w = threadIdx.x >> 5, l = threadIdx.x & 31;
    int row = blockIdx.x * 8 + w;
    float m = -INFINITY, s = 0.f;
    for (int p = l; p < NSLAB; p += 32) {
        float2 ps = part[(size_t)row * NSLAB + p];
        float M = fmaxf(m, ps.x);
        s = s * __expf(m - M) + ps.y * __expf(ps.x - M);
        m = M;
    }
#pragma unroll
    for (int st = 16; st > 0; st >>= 1) {
        float m2 = __shfl_xor_sync(0xFFFFFFFF, m, st);
        float s2 = __shfl_xor_sync(0xFFFFFFFF, s, st);
        float M = fmaxf(m, m2);
        s = s * __expf(m - M) + s2 * __expf(m2 - M);
        m = M;
    }
    if (l == 0) rowloss[row] = m + logf(s) - zt[row];
}

__global__ void loss_reduce_kernel(const float* __restrict__ rowloss, float* __restrict__ out)
{
    __shared__ float red[256];
    int tid = threadIdx.x;
    float s = 0.f;
    for (int i = tid; i < ROWS; i += 256) s += rowloss[i];
    red[tid] = s;
    __syncthreads();
    for (int st = 128; st > 0; st >>= 1) {
        if (tid < st) red[tid] += red[tid + st];
        __syncthreads();
    }
    if (tid == 0) out[0] = red[0] * (1.0f / ROWS);
}

// ---------------------------------------------------------------------------
// Host
// ---------------------------------------------------------------------------
extern "C" void kernel_launch(void* const* d_in, const int* in_sizes, int n_in,
                              void* d_out, int out_size)
{
    const int*   idx     = (const int*)  d_in[0];
    const int*   targets = (const int*)  d_in[1];
    const float* tok_emb = (const float*)d_in[2];
    const float* pos_emb = (const float*)d_in[3];
    const float* ln1_g   = (const float*)d_in[4];
    const float* ln1_b   = (const float*)d_in[5];
    const float* Wq      = (const float*)d_in[6];
    const float* Wk      = (const float*)d_in[7];
    const float* Wv      = (const float*)d_in[8];
    const float* Wp      = (const float*)d_in[9];
    const float* bp      = (const float*)d_in[10];
    const float* ln2_g   = (const float*)d_in[11];
    const float* ln2_b   = (const float*)d_in[12];
    const float* W1      = (const float*)d_in[13];
    const float* b1      = (const float*)d_in[14];
    const float* W2      = (const float*)d_in[15];
    const float* b2      = (const float*)d_in[16];
    const float* lnf_g   = (const float*)d_in[17];
    const float* lnf_b   = (const float*)d_in[18];
    const float* Wlm     = (const float*)d_in[19];
    const float* blm     = (const float*)d_in[20];

    float* out      = (float*)d_out;
    float* attn_out = out + 1;

    float *x, *rl, *ztp;
    float2* part;
    __half *hbuf, *qkvh, *ohb, *ffh, *wth;
    cudaGetSymbolAddress((void**)&x,    g_x);
    cudaGetSymbolAddress((void**)&hbuf, g_hh);
    cudaGetSymbolAddress((void**)&qkvh, g_qkvh);
    cudaGetSymbolAddress((void**)&ohb,  g_oh);
    cudaGetSymbolAddress((void**)&ffh,  g_ffh);
    cudaGetSymbolAddress((void**)&wth,  g_wth);
    cudaGetSymbolAddress((void**)&part, g_part);
    cudaGetSymbolAddress((void**)&ztp,  g_zt);
    cudaGetSymbolAddress((void**)&rl,   g_rl);

    cudaFuncSetAttribute(gemm_mma<0>, cudaFuncAttributeMaxDynamicSharedMemorySize, GEMM_SMEM);
    cudaFuncSetAttribute(gemm_mma<1>, cudaFuncAttributeMaxDynamicSharedMemorySize, GEMM_SMEM);
    cudaFuncSetAttribute(gemm_mma<2>, cudaFuncAttributeMaxDynamicSharedMemorySize, GEMM_SMEM);
    cudaFuncSetAttribute(gemm_mma<3>, cudaFuncAttributeMaxDynamicSharedMemorySize, GEMM_SMEM);
    cudaFuncSetAttribute(gemm_lm,     cudaFuncAttributeMaxDynamicSharedMemorySize, GEMM_SMEM);
    cudaFuncSetAttribute(attn_hmma,   cudaFuncAttributeMaxDynamicSharedMemorySize, ATT_SMEM);

    embed_kernel<<<ROWS, 256>>>(idx, tok_emb, pos_emb, x);

    for (int l = 0; l < NL; l++) {
        ln_kernel<<<ROWS / 8, 256>>>(x, ln1_g + (size_t)l * DIM, ln1_b + (size_t)l * DIM, hbuf);
        pack_qkv_t<<<dim3(HS / 32, DIM / 32, 3 * NH), dim3(32, 8)>>>(Wq, Wk, Wv, wth, l);
        gemm_mma<3><<<dim3(3 * DIM / 128, ROWS / 128), 128, GEMM_SMEM>>>(
            hbuf, wth, nullptr, nullptr, qkvh, 3 * DIM, DIM);

        float* attnL = attn_out + (size_t)l * BATCH * NH * SEQ * SEQ;
        attn_hmma<<<dim3(SEQ / SQ, BATCH * NH), 256, ATT_SMEM>>>(qkvh, attnL, ohb);

        transpose_k<<<dim3(DIM / 32, DIM / 32), dim3(32, 8)>>>(
            Wp + (size_t)l * DIM * DIM, wth, DIM, DIM);
        gemm_mma<1><<<dim3(DIM / 128, ROWS / 128), 128, GEMM_SMEM>>>(
            ohb, wth, bp + (size_t)l * DIM, x, x, DIM, DIM);

        ln_kernel<<<ROWS / 8, 256>>>(x, ln2_g + (size_t)l * DIM, ln2_b + (size_t)l * DIM, hbuf);

        transpose_k<<<dim3(FFD / 32, DIM / 32), dim3(32, 8)>>>(
            W1 + (size_t)l * DIM * FFD, wth, DIM, FFD);
        gemm_mma<2><<<dim3(FFD / 128, ROWS / 128), 128, GEMM_SMEM>>>(
            hbuf, wth, b1 + (size_t)l * FFD, nullptr, ffh, FFD, DIM);

        transpose_k<<<dim3(DIM / 32, FFD / 32), dim3(32, 8)>>>(
            W2 + (size_t)l * FFD * DIM, wth, FFD, DIM);
        gemm_mma<1><<<dim3(DIM / 128, ROWS / 128), 128, GEMM_SMEM>>>(
            ffh, wth, b2 + (size_t)l * DIM, x, x, DIM, FFD);
    }

    ln_kernel<<<ROWS / 8, 256>>>(x, lnf_g, lnf_b, hbuf);
    transpose_k<<<dim3(VOCAB / 32, DIM / 32), dim3(32, 8)>>>(Wlm, wth, DIM, VOCAB);
    gemm_lm<<<dim3(NSLAB, ROWS / 128), 128, GEMM_SMEM>>>(
        hbuf, wth, blm, targets, part, ztp, DIM);

    loss_from_parts<<<ROWS / 8, 256>>>(part, ztp, rl);
    loss_reduce_kernel<<<1, 256>>>(rl, out);
}